// round 9
// baseline (speedup 1.0000x reference)
#include <cuda_runtime.h>
#include <cuda_bf16.h>

#define NP 8192
#define GD 48                      // cells per dimension (cell = 0.2 = 2h)
#define NCELLS (GD * GD * GD)      // 110592
#define CAP 20                     // slots per cell (Poisson(~4.2) -> P(>20) ~ 1e-9)
#define CELL_INV 5.0f              // 1 / 0.2
#define GMIN 4.8f                  // grid covers [-4.8, 4.8); outliers clamp (safe)
#define INV_H 10.0f
#define EPS 1e-10f

#define NBLK 256
#define NTHR 256                   // NBLK*NTHR = NP*8

// 8 / (PI * H^3) — matches reference constant
__device__ __constant__ float kNorm = (float)(8.0 / (3.14159265 * 0.001));

// Invariants across calls (input is identical every call):
//  - d_cnt all-zero at entry (first call: .bss; later: phase A zeroed the
//    touched set recorded in d_pcell by the previous call's phase B).
//  - bar_cnt == 0, bar_sense == 0 at entry (sense flips twice per call).
__device__ int      d_cnt[NCELLS];
__device__ float4   d_slot[NCELLS * CAP];
__device__ int      d_pcell[NP];
__device__ unsigned bar_cnt;
__device__ unsigned bar_sense;

__device__ __forceinline__ int cell_coord(float v) {
    int c = __float2int_rd((v + GMIN) * CELL_INV);
    return min(max(c, 0), GD - 1);
}

// Base cell of the 2-cell-per-axis support window; in [0, GD-2].
__device__ __forceinline__ int cell_base(float v) {
    float u  = (v + GMIN) * CELL_INV;
    int   ix = __float2int_rd(u);
    int   b  = ix + ((u - (float)ix < 0.5f) ? -1 : 0);
    return min(max(b, 0), GD - 2);
}

// Sense-reversing grid barrier. Requires all NBLK blocks resident (proven:
// 4 blocks/SM occupancy * 148 SMs = 592 >= 256, all wave-1).
__device__ __forceinline__ void grid_barrier(unsigned& sense) {
    __syncthreads();
    if (threadIdx.x == 0) {
        sense ^= 1u;
        __threadfence();
        unsigned old = atomicAdd(&bar_cnt, 1u);
        if (old == NBLK - 1) {
            bar_cnt = 0u;                    // only spinners read bar_sense
            __threadfence();
            bar_sense = sense;               // release
        } else {
            while (*(volatile unsigned*)&bar_sense != sense) { }
        }
        __threadfence();
    }
    __syncthreads();
}

__global__ void __launch_bounds__(NTHR) fused_kernel(
    const float* __restrict__ pos, float* __restrict__ out)
{
    unsigned sense = 0u;
    const int t = blockIdx.x * NTHR + threadIdx.x;   // 0 .. NP*8-1
    const int i = t >> 3;
    const int s = t & 7;

    // ---- Phase A: zero previous call's touched cells ----
    if (s == 0) d_cnt[d_pcell[i]] = 0;

    grid_barrier(sense);

    // ---- Phase B: build ----
    const float xi = pos[3 * i + 0];
    const float yi = pos[3 * i + 1];
    const float zi = pos[3 * i + 2];

    if (s == 0) {
        int c = (cell_coord(zi) * GD + cell_coord(yi)) * GD + cell_coord(xi);
        int slot = atomicAdd(&d_cnt[c], 1);
        if (slot < CAP) d_slot[c * CAP + slot] = make_float4(xi, yi, zi, 0.0f);
        d_pcell[i] = c;
    }

    grid_barrier(sense);

    // ---- Phase C: query (8 lanes per particle, one cell each) ----
    const int cx = cell_base(xi) + (s & 1);
    const int cy = cell_base(yi) + ((s >> 1) & 1);
    const int cz = cell_base(zi) + (s >> 2);
    const int c  = (cz * GD + cy) * GD + cx;

    float acc = 0.0f;
    int n = min(__ldcg(&d_cnt[c]), CAP);          // L1-bypass: cross-SM data
    const float4* sp = &d_slot[c * CAP];
    for (int e = 0; e < n; e++) {
        float4 p = __ldcg(&sp[e]);
        float ddx = p.x - xi;
        float ddy = p.y - yi;
        float ddz = p.z - zi;
        float r2 = fmaf(ddx, ddx, fmaf(ddy, ddy, fmaf(ddz, ddz, EPS)));
        float r;
        asm("sqrt.approx.f32 %0, %1;" : "=f"(r) : "f"(r2));
        float q   = r * INV_H;
        float qm1 = q - 1.0f;
        float wi  = fmaf(q * q * 6.0f, qm1, 1.0f);   // 1 - 6q^2 + 6q^3
        float wo  = -2.0f * qm1 * qm1 * qm1;         // 2(1-q)^3
        float w   = (q <= 0.5f) ? wi : wo;
        acc += (q <= 1.0f) ? w : 0.0f;
    }

    // reduce the 8-lane group (same warp, contiguous lanes)
    acc += __shfl_xor_sync(0xFFFFFFFFu, acc, 1);
    acc += __shfl_xor_sync(0xFFFFFFFFu, acc, 2);
    acc += __shfl_xor_sync(0xFFFFFFFFu, acc, 4);

    if (s == 0) out[i] = acc * kNorm;
}

extern "C" void kernel_launch(void* const* d_in, const int* in_sizes, int n_in,
                              void* d_out, int out_size)
{
    const float* pos = (const float*)d_in[0];
    float* out = (float*)d_out;
    (void)in_sizes; (void)n_in; (void)out_size;

    fused_kernel<<<NBLK, NTHR>>>(pos, out);
}

// round 10
// speedup vs baseline: 1.1517x; 1.1517x over previous
#include <cuda_runtime.h>
#include <cuda_bf16.h>

#define NP 8192
#define GD 48                      // cells per dimension (cell = 0.2 = 2h)
#define NCELLS (GD * GD * GD)      // 110592
#define CAP 20                     // slots per cell (Poisson(~4.2) -> P(>20) ~ 1e-9)
#define CELL_INV 5.0f              // 1 / 0.2
#define GMIN 4.8f                  // grid covers [-4.8, 4.8); outliers clamp (safe)
#define INV_H 10.0f
#define EPS 1e-10f

#define NBLK1 64
#define NTHR1 128                  // NBLK1*NTHR1 = NP

// 8 / (PI * H^3) — matches reference constant
__device__ __constant__ float kNorm = (float)(8.0 / (3.14159265 * 0.001));

// Invariants at entry of every call (input identical every call):
//  - d_cnt all-zero (first call: .bss; later: phase A zeroed the touched set
//    recorded in d_pcell by the previous call's phase B).
//  - bar_cnt == 0 (counter-wrap barrier self-resets).
__device__ int      d_cnt[NCELLS];
__device__ float4   d_slot[NCELLS * CAP];
__device__ int      d_pcell[NP];
__device__ unsigned bar_cnt;

__device__ __forceinline__ int cell_coord(float v) {
    int c = __float2int_rd((v + GMIN) * CELL_INV);
    return min(max(c, 0), GD - 1);
}

// Base cell of the 2-cell-per-axis support window; in [0, GD-2].
__device__ __forceinline__ int cell_base(float v) {
    float u  = (v + GMIN) * CELL_INV;
    int   ix = __float2int_rd(u);
    int   b  = ix + ((u - (float)ix < 0.5f) ? -1 : 0);
    return min(max(b, 0), GD - 2);
}

// Counter-wrap grid barrier (state returns to 0 => graph-replay safe).
// All NBLK1 blocks trivially resident (64 blocks, 128 thr, low regs).
__device__ __forceinline__ void grid_barrier_64() {
    __syncthreads();
    if (threadIdx.x == 0) {
        __threadfence();                          // publish phase-A writes
        unsigned old = atomicAdd(&bar_cnt, 1u);
        if (old == NBLK1 - 1) {
            __threadfence();
            *(volatile unsigned*)&bar_cnt = 0u;   // release; self-reset
        } else {
            while (*(volatile unsigned*)&bar_cnt != 0u) { }
        }
        __threadfence();                          // acquire
    }
    __syncthreads();
}

// Phase A: zero previous call's touched cells. Barrier. Phase B: build.
__global__ void __launch_bounds__(NTHR1) prep_kernel(const float* __restrict__ pos)
{
    const int i  = blockIdx.x * NTHR1 + threadIdx.x;
    const int pc = d_pcell[i];

    const float xi = pos[3 * i + 0];
    const float yi = pos[3 * i + 1];
    const float zi = pos[3 * i + 2];

    d_cnt[pc] = 0;                 // racing identical zero-stores: benign

    grid_barrier_64();

    const int c = (cell_coord(zi) * GD + cell_coord(yi)) * GD + cell_coord(xi);
    int slot = atomicAdd(&d_cnt[c], 1);
    if (slot < CAP) d_slot[c * CAP + slot] = make_float4(xi, yi, zi, 0.0f);
    if (c != pc) d_pcell[i] = c;   // only first call actually stores
}

// 8 lanes per particle; lane sub-id s in [0,8) owns cell (bx+sx, by+sy, bz+sz).
__global__ void __launch_bounds__(256) query_kernel(
    const float* __restrict__ pos, float* __restrict__ out)
{
    int t = blockIdx.x * blockDim.x + threadIdx.x;   // NP*8 threads
    int i = t >> 3;
    int s = t & 7;

    const float xi = pos[3 * i + 0];
    const float yi = pos[3 * i + 1];
    const float zi = pos[3 * i + 2];

    const int cx = cell_base(xi) + (s & 1);
    const int cy = cell_base(yi) + ((s >> 1) & 1);
    const int cz = cell_base(zi) + (s >> 2);
    const int c  = (cz * GD + cy) * GD + cx;

    float acc = 0.0f;
    int n = min(d_cnt[c], CAP);
    const float4* sp = &d_slot[c * CAP];
    for (int e = 0; e < n; e++) {
        float4 p = sp[e];
        float ddx = p.x - xi;
        float ddy = p.y - yi;
        float ddz = p.z - zi;
        float r2 = fmaf(ddx, ddx, fmaf(ddy, ddy, fmaf(ddz, ddz, EPS)));
        float r;
        asm("sqrt.approx.f32 %0, %1;" : "=f"(r) : "f"(r2));
        float q   = r * INV_H;
        float qm1 = q - 1.0f;
        float wi  = fmaf(q * q * 6.0f, qm1, 1.0f);   // 1 - 6q^2 + 6q^3
        float wo  = -2.0f * qm1 * qm1 * qm1;         // 2(1-q)^3
        float w   = (q <= 0.5f) ? wi : wo;
        acc += (q <= 1.0f) ? w : 0.0f;
    }

    // reduce the 8-lane group (same warp, contiguous lanes)
    acc += __shfl_xor_sync(0xFFFFFFFFu, acc, 1);
    acc += __shfl_xor_sync(0xFFFFFFFFu, acc, 2);
    acc += __shfl_xor_sync(0xFFFFFFFFu, acc, 4);

    if (s == 0) out[i] = acc * kNorm;
}

extern "C" void kernel_launch(void* const* d_in, const int* in_sizes, int n_in,
                              void* d_out, int out_size)
{
    const float* pos = (const float*)d_in[0];
    float* out = (float*)d_out;
    (void)in_sizes; (void)n_in; (void)out_size;

    prep_kernel<<<NBLK1, NTHR1>>>(pos);              // 64 blocks
    query_kernel<<<NP * 8 / 256, 256>>>(pos, out);   // 256 blocks
}